// round 11
// baseline (speedup 1.0000x reference)
#include <cuda_runtime.h>
#include <cooperative_groups.h>
#include <math.h>

namespace cg = cooperative_groups;

#define Mdim 512
#define Ndim 2048
#define Bsz  4
#define Lnum 20
#define CAP  24576            // global nnz cap (E[nnz]=20971)
#define ROWCAP 96
#define MNdim (Mdim*Ndim)
#define EPSV 1e-6f
#define NTH  1024
#define CLSZ 2
#define RPC (Mdim/CLSZ)       // 256 rows per CTA
#define CPC (Ndim/CLSZ)       // 1024 cols per CTA
#define LCAP 11264            // per-CTA entry cap (E=10486, +~7.7 sigma)
#define SLOTS (CLSZ*LCAP)     // 22528

#define CLUSTER_ARRIVE() asm volatile("barrier.cluster.arrive.aligned;" ::: "memory")
#define CLUSTER_WAIT()   asm volatile("barrier.cluster.wait.aligned;" ::: "memory")

// ---------------- device scratch ----------------
__device__ int            g_deg[Mdim];
__device__ int            g_rowptr[Mdim + 1];
__device__ int            g_nnz;
__device__ unsigned short g_stage[Mdim * ROWCAP];
__device__ unsigned       g_lin[CAP];          // CSR linear indices
__device__ unsigned short g_permS[SLOTS];      // slice-local CSC pos -> local CSR pos
__device__ unsigned       g_linS[SLOTS];       // slice-local CSC linear indices
__device__ int            g_scnt[CLSZ];
__device__ int            g_colptr[CLSZ * (Ndim + 1)];
__device__ __align__(16) float2 g_wmn[(size_t)Lnum * SLOTS]; // {mwde[l], wde[l+1]} CSC slice-local
__device__ float          g_rho[Lnum];

// ---------------- P1: block per row — degree + staged column list ----------------
__global__ void k_prep1(const float4* __restrict__ H4) {
    __shared__ int s_cnt;
    __shared__ unsigned short s_cols[ROWCAP];
    const int i = blockIdx.x;
    const int t = threadIdx.x;       // 512 threads, one float4 each
    const int lane = t & 31;
    if (t == 0) s_cnt = 0;
    __syncthreads();
    float4 v = H4[(size_t)i * (Ndim / 4) + t];
    int cnt = (v.x != 0.0f) + (v.y != 0.0f) + (v.z != 0.0f) + (v.w != 0.0f);
    int sc = cnt;
    for (int o = 1; o < 32; o <<= 1) {
        int u = __shfl_up_sync(0xffffffffu, sc, o);
        if (lane >= o) sc += u;
    }
    int total = __shfl_sync(0xffffffffu, sc, 31);
    int base = 0;
    if (lane == 31 && total) base = atomicAdd(&s_cnt, total);
    base = __shfl_sync(0xffffffffu, base, 31);
    int idx = base + sc - cnt;
    int c = t * 4;
    if (v.x != 0.0f && idx < ROWCAP) s_cols[idx++] = (unsigned short)c;
    if (v.y != 0.0f && idx < ROWCAP) s_cols[idx++] = (unsigned short)(c + 1);
    if (v.z != 0.0f && idx < ROWCAP) s_cols[idx++] = (unsigned short)(c + 2);
    if (v.w != 0.0f && idx < ROWCAP) s_cols[idx++] = (unsigned short)(c + 3);
    __syncthreads();
    int d = min(s_cnt, ROWCAP);
    if (t == 0) g_deg[i] = d;
    if (t < d) g_stage[i * ROWCAP + t] = s_cols[t];
}

// ---------------- P2: scan + expand CSR + softmax + zero out ----------------
__global__ void k_prep2(const float* __restrict__ rhos, float* __restrict__ out) {
    __shared__ int s[Mdim];
    const int t = threadIdx.x;
    s[t] = g_deg[t];
    __syncthreads();
    for (int off = 1; off < Mdim; off <<= 1) {
        int v = (t >= off) ? s[t - off] : 0;
        __syncthreads();
        s[t] += v;
        __syncthreads();
    }
    g_rowptr[t + 1] = s[t];
    if (t == 0) g_rowptr[0] = 0;
    if (t == Mdim - 1) g_nnz = s[Mdim - 1];
    int st = s[t] - g_deg[t];
    int d  = g_deg[t];
    unsigned lbase = (unsigned)(t * Ndim);
    for (int k = 0; k < d; k++) {
        int idx = st + k;
        if (idx < CAP) g_lin[idx] = lbase + g_stage[t * ROWCAP + k];
    }
    if (t == 0) {
        *out = 0.0f;
        float mx = -1e30f;
        for (int l = 0; l < Lnum; l++) mx = fmaxf(mx, rhos[l]);
        float e[Lnum], sm = 0.0f;
        for (int l = 0; l < Lnum; l++) { e[l] = expf(rhos[l] - mx); sm += e[l]; }
        float inv = 1.0f / sm;
        for (int l = 0; l < Lnum; l++) g_rho[l] = e[l] * inv;
    }
}

// ---------------- P3: per-slice CSC (slice-local layout), grid=CLSZ ----------------
__global__ void k_prep3() {
    __shared__ int s_hist[Ndim];
    __shared__ int s_cp[Ndim + 1];
    __shared__ int s_wsum[32];
    const int blk = blockIdx.x;
    const int t = threadIdx.x;
    const int lane = t & 31;
    const int wid = t >> 5;
    const int r0 = blk * RPC;
    const int kbase = g_rowptr[r0];
    int kend = g_rowptr[r0 + RPC];
    if (kend - kbase > LCAP) kend = kbase + LCAP;
    const int cnt = kend - kbase;

    s_hist[t] = 0; s_hist[t + 1024] = 0;
    __syncthreads();
    for (int k = t; k < cnt; k += 1024)
        atomicAdd(&s_hist[g_lin[kbase + k] & (Ndim - 1)], 1);
    __syncthreads();
    int a = s_hist[2 * t], b = s_hist[2 * t + 1];
    int ssum = a + b;
    int sc = ssum;
    for (int o = 1; o < 32; o <<= 1) {
        int u = __shfl_up_sync(0xffffffffu, sc, o);
        if (lane >= o) sc += u;
    }
    if (lane == 31) s_wsum[wid] = sc;
    __syncthreads();
    if (wid == 0) {
        int v = s_wsum[lane];
        for (int o = 1; o < 32; o <<= 1) {
            int u = __shfl_up_sync(0xffffffffu, v, o);
            if (lane >= o) v += u;
        }
        s_wsum[lane] = v;
    }
    __syncthreads();
    int incl = sc + ((wid > 0) ? s_wsum[wid - 1] : 0);
    int excl = incl - ssum;
    s_cp[2 * t] = excl;
    s_cp[2 * t + 1] = excl + a;
    if (t == 1023) s_cp[Ndim] = incl;
    __syncthreads();
    s_hist[2 * t] = s_cp[2 * t];
    s_hist[2 * t + 1] = s_cp[2 * t + 1];
    g_colptr[blk * (Ndim + 1) + 2 * t]     = s_cp[2 * t];
    g_colptr[blk * (Ndim + 1) + 2 * t + 1] = s_cp[2 * t + 1];
    if (t == 1023) g_colptr[blk * (Ndim + 1) + Ndim] = s_cp[Ndim];
    if (t == 0) g_scnt[blk] = cnt;
    __syncthreads();
    for (int k = t; k < cnt; k += 1024) {
        unsigned lin = g_lin[kbase + k];
        int j = lin & (Ndim - 1);
        int pos = atomicAdd(&s_hist[j], 1);
        g_permS[blk * LCAP + pos] = (unsigned short)k;
        g_linS[blk * LCAP + pos]  = lin;
    }
}

// ---------------- P4: gather — one thread per entry, all layers ----------------
__global__ void k_gather(const float* __restrict__ wde, const float* __restrict__ mwde) {
    const int e = blockIdx.x * 256 + threadIdx.x;     // 0..SLOTS-1
    if (e >= SLOTS) return;
    const int blk = e / LCAP;
    const int k = e - blk * LCAP;
    const bool valid = (k < g_scnt[blk]);
    const unsigned lin = valid ? g_linS[e] : 0u;
    float wm[Lnum], wn[Lnum];
    #pragma unroll
    for (int l = 0; l < Lnum; l++) wm[l] = __ldg(&mwde[(size_t)l * MNdim + lin]);
    #pragma unroll
    for (int l = 0; l < Lnum; l++) wn[l] = __ldg(&wde[(size_t)l * MNdim + lin]);
    #pragma unroll
    for (int l = 0; l < Lnum; l++) {
        float2 p;
        p.x = wm[l];
        p.y = (l + 1 < Lnum) ? wn[l + 1] : 0.0f;
        g_wmn[(size_t)l * SLOTS + e] = p;
    }
}

// ---------------- main BP recurrence: CLSZ=2, single cluster.sync per layer ----------------
// floats: msgs LCAP | colC N | colP 2N | belP 2N | sign2 R | offf R | err C | misc 96 |
// int rpt R+4 ; u16: lin LCAP | perm LCAP | cptr N+4
#define SMEM_BYTES ((LCAP + 5*Ndim + 2*RPC + CPC + 96 + (RPC + 4)) * 4 \
                    + (2*LCAP + Ndim + 4) * 2)

__global__ void __launch_bounds__(NTH, 1) __cluster_dims__(CLSZ, 1, 1)
k_main(const int*   __restrict__ synd,
       const int*   __restrict__ errs,
       const float* __restrict__ llrs,
       const float* __restrict__ wllr,
       const float* __restrict__ mwllr,
       const float* __restrict__ resw,
       float* __restrict__ out)
{
    extern __shared__ char sm_raw[];
    float*  s_msgs  = (float*)sm_raw;                // LCAP
    float*  s_colC  = s_msgs + LCAP;                 // N (combined, read in row pass)
    float*  s_colP  = s_colC + Ndim;                 // 2N (parity partials)
    float*  s_belP  = s_colP + 2 * Ndim;             // 2N
    float*  s_sign2 = s_belP + 2 * Ndim;             // R
    float*  s_offf  = s_sign2 + RPC;                 // R
    float*  s_err   = s_offf + RPC;                  // C
    float*  s_resw  = s_err + CPC;                   // 32
    float*  s_rho   = s_resw + 32;                   // 32
    float*  s_lacc  = s_rho + 32;                    // 32
    int*    s_rpt   = (int*)(s_lacc + 32);           // R+1 (+pad)
    unsigned short* s_lin  = (unsigned short*)(s_rpt + RPC + 4);  // LCAP
    unsigned short* s_perm = s_lin + LCAP;                         // LCAP
    unsigned short* s_cptr = s_perm + LCAP;                        // N+1 (+pad)

    cg::cluster_group cl = cg::this_cluster();
    const int rank = (int)cl.block_rank();
    const int peer = rank ^ 1;
    const int b    = blockIdx.x / CLSZ;
    const int tid  = threadIdx.x;
    const int lane = tid & 31;
    const int wid  = tid >> 5;
    const float OME = 1.0f - EPSV;

    const int r0 = rank * RPC;
    const int kbase = g_rowptr[r0];
    int kend = g_rowptr[r0 + RPC];
    if (kend - kbase > LCAP) kend = kbase + LCAP;
    const int cnt = kend - kbase;

    // ---- prologue ----
    for (int k = tid; k < cnt; k += NTH) {
        s_lin[k]  = (unsigned short)(g_lin[kbase + k] & (Ndim - 1));
        s_perm[k] = g_permS[rank * LCAP + k];
        s_msgs[k] = 0.0f;
    }
    for (int j = tid; j <= Ndim; j += NTH)
        s_cptr[j] = (unsigned short)g_colptr[rank * (Ndim + 1) + j];
    if (tid <= RPC) s_rpt[tid] = g_rowptr[r0 + tid] - kbase;
    if (tid < RPC) {
        int row = r0 + tid;
        s_sign2[tid] = 2.0f * (1.0f - 2.0f * (float)synd[b * Mdim + row]);
        int d = g_rowptr[row + 1] - g_rowptr[row];
        s_offf[tid] = powf(OME, (float)(Ndim - d));
    }
    // err: owned CPC slice (tid < 1024 == NTH covers it)
    s_err[tid] = 1.0f - (float)errs[b * Ndim + rank * CPC + tid];
    if (tid < Lnum) { s_resw[tid] = resw[tid]; s_rho[tid] = g_rho[tid]; }
    for (int j = tid; j < Ndim; j += NTH)
        s_colC[j] = llrs[j] * wllr[j];     // layer-0 combined column input
    __syncthreads();

    float acc = 0.0f;
    for (int l = 0; l < Lnum; l++) {
        const float rw = s_resw[l];
        const int parW = l & 1;

        // ---- phase A (l>0): combine prev partials by READING peer + prev-layer loss ----
        if (l > 0) {
            const int parR = parW ^ 1;
            if (tid < Ndim / 4) {
                // colC for ALL N columns
                const int f4 = tid;
                float4 lv = ((const float4*)llrs)[f4];
                float4 wv = ((const float4*)(wllr + (size_t)l * Ndim))[f4];
                float* own = s_colP + parR * Ndim;
                float4 a = ((const float4*)own)[f4];
                float4 p = ((const float4*)cl.map_shared_rank(own, peer))[f4];
                float4 s;
                s.x = lv.x * wv.x + a.x + p.x;
                s.y = lv.y * wv.y + a.y + p.y;
                s.z = lv.z * wv.z + a.z + p.z;
                s.w = lv.w * wv.w + a.w + p.w;
                ((float4*)s_colC)[f4] = s;
            } else if (tid < Ndim / 4 + CPC / 4) {
                // belief combine + loss of layer l-1 for owned slice
                const int f4l = tid - Ndim / 4;              // 0..255
                const int f4 = rank * (CPC / 4) + f4l;
                float4 lv = ((const float4*)llrs)[f4];
                float4 wv = ((const float4*)(mwllr + (size_t)(l - 1) * Ndim))[f4];
                float* own = s_belP + parR * Ndim;
                float4 a = ((const float4*)own)[f4];
                float4 p = ((const float4*)cl.map_shared_rank(own, peer))[f4];
                float4 x;
                x.x = lv.x * wv.x + a.x + p.x;
                x.y = lv.y * wv.y + a.y + p.y;
                x.z = lv.z * wv.z + a.z + p.z;
                x.w = lv.w * wv.w + a.w + p.w;
                const int jj = f4l * 4;
                float ls = 0.0f;
                ls += fmaxf(x.x, 0.0f) + log1pf(__expf(-fabsf(x.x))) - s_err[jj]     * x.x;
                ls += fmaxf(x.y, 0.0f) + log1pf(__expf(-fabsf(x.y))) - s_err[jj + 1] * x.y;
                ls += fmaxf(x.z, 0.0f) + log1pf(__expf(-fabsf(x.z))) - s_err[jj + 2] * x.z;
                ls += fmaxf(x.w, 0.0f) + log1pf(__expf(-fabsf(x.w))) - s_err[jj + 3] * x.w;
                acc += s_rho[l - 1] * ls;
            }
            __syncthreads();
        }

        // ---- phase B: fused warp-per-row (tanh + product + message update) ----
        for (int rr = wid; rr < RPC; rr += 32) {
            const int st = s_rpt[rr], en = s_rpt[rr + 1];
            const int k0 = st + lane, k1 = k0 + 32, k2 = k1 + 32;
            float d0 = 1.0f, d1 = 1.0f, d2 = 1.0f;
            float prod = 1.0f;
            if (k0 < en) {
                float men = s_colC[s_lin[k0]] - s_msgs[k0];
                asm("tanh.approx.f32 %0, %1;" : "=f"(d0) : "f"(0.5f * men));
                if (d0 == 0.0f) d0 = 1.0f;
                d0 = fminf(fmaxf(d0, -OME), OME);
                prod *= d0;
            }
            if (k1 < en) {
                float men = s_colC[s_lin[k1]] - s_msgs[k1];
                asm("tanh.approx.f32 %0, %1;" : "=f"(d1) : "f"(0.5f * men));
                if (d1 == 0.0f) d1 = 1.0f;
                d1 = fminf(fmaxf(d1, -OME), OME);
                prod *= d1;
            }
            if (k2 < en) {
                float men = s_colC[s_lin[k2]] - s_msgs[k2];
                asm("tanh.approx.f32 %0, %1;" : "=f"(d2) : "f"(0.5f * men));
                if (d2 == 0.0f) d2 = 1.0f;
                d2 = fminf(fmaxf(d2, -OME), OME);
                prod *= d2;
            }
            #pragma unroll
            for (int o = 16; o; o >>= 1) prod *= __shfl_xor_sync(0xffffffffu, prod, o);
            const float P = prod * s_offf[rr];
            const float sg = s_sign2[rr];
            if (k0 < en) {
                float r = __fdividef(P, d0);
                float ath = (fabsf(r) < 6.25e-3f) ? r * (1.0f + (1.0f / 3.0f) * r * r)
                                                  : atanhf(r);
                s_msgs[k0] = sg * ath + rw * s_msgs[k0];
            }
            if (k1 < en) {
                float r = __fdividef(P, d1);
                float ath = (fabsf(r) < 6.25e-3f) ? r * (1.0f + (1.0f / 3.0f) * r * r)
                                                  : atanhf(r);
                s_msgs[k1] = sg * ath + rw * s_msgs[k1];
            }
            if (k2 < en) {
                float r = __fdividef(P, d2);
                float ath = (fabsf(r) < 6.25e-3f) ? r * (1.0f + (1.0f / 3.0f) * r * r)
                                                  : atanhf(r);
                s_msgs[k2] = sg * ath + rw * s_msgs[k2];
            }
        }
        __syncthreads();

        // ---- phase C: column-parallel CSC partial sums, weights direct from L2 ----
        {
            float* colW = s_colP + parW * Ndim;
            float* belW = s_belP + parW * Ndim;
            const float2* gw = &g_wmn[(size_t)l * SLOTS + rank * LCAP];
            const int j0 = tid * 2;
            #pragma unroll
            for (int jj = 0; jj < 2; jj++) {
                const int j = j0 + jj;
                const int st = s_cptr[j], en = s_cptr[j + 1];
                float cs = 0.0f, bs = 0.0f;
                for (int t = st; t < en; t++) {
                    float m = s_msgs[s_perm[t]];
                    float2 w = __ldg(&gw[t]);
                    bs += m * w.x;
                    cs += m * w.y;
                }
                belW[j] = bs;
                colW[j] = cs;
            }
        }
        CLUSTER_ARRIVE();
        CLUSTER_WAIT();
    }

    // ---- tail: loss of final layer ----
    {
        const int parR = (Lnum - 1) & 1;
        if (tid >= Ndim / 4 && tid < Ndim / 4 + CPC / 4) {
            const int f4l = tid - Ndim / 4;
            const int f4 = rank * (CPC / 4) + f4l;
            float4 lv = ((const float4*)llrs)[f4];
            float4 wv = ((const float4*)(mwllr + (size_t)(Lnum - 1) * Ndim))[f4];
            float* own = s_belP + parR * Ndim;
            float4 a = ((const float4*)own)[f4];
            float4 p = ((const float4*)cl.map_shared_rank(own, peer))[f4];
            float4 x;
            x.x = lv.x * wv.x + a.x + p.x;
            x.y = lv.y * wv.y + a.y + p.y;
            x.z = lv.z * wv.z + a.z + p.z;
            x.w = lv.w * wv.w + a.w + p.w;
            const int jj = f4l * 4;
            float ls = 0.0f;
            ls += fmaxf(x.x, 0.0f) + log1pf(__expf(-fabsf(x.x))) - s_err[jj]     * x.x;
            ls += fmaxf(x.y, 0.0f) + log1pf(__expf(-fabsf(x.y))) - s_err[jj + 1] * x.y;
            ls += fmaxf(x.z, 0.0f) + log1pf(__expf(-fabsf(x.z))) - s_err[jj + 2] * x.z;
            ls += fmaxf(x.w, 0.0f) + log1pf(__expf(-fabsf(x.w))) - s_err[jj + 3] * x.w;
            acc += s_rho[Lnum - 1] * ls;
        }
        CLUSTER_ARRIVE();     // no CTA exits while peer still reads its smem
        CLUSTER_WAIT();
    }

    // ---- loss reduce: acc lives in warps 16..23 (threads 512..767) ----
    for (int o = 16; o; o >>= 1) acc += __shfl_xor_sync(0xffffffffu, acc, o);
    if (wid >= 16 && wid < 24 && lane == 0) s_lacc[wid - 16] = acc;
    __syncthreads();
    if (tid == 0) {
        float s = 0.0f;
        #pragma unroll
        for (int w = 0; w < 8; w++) s += s_lacc[w];
        atomicAdd(out, s * (1.0f / (float)Bsz));
    }
}

// ---------------- host launcher ----------------
extern "C" void kernel_launch(void* const* d_in, const int* in_sizes, int n_in,
                              void* d_out, int out_size) {
    const int*   synd  = (const int*)d_in[0];
    const int*   errs  = (const int*)d_in[1];
    const float* H     = (const float*)d_in[2];
    const float* llrs  = (const float*)d_in[3];
    const float* wde   = (const float*)d_in[4];
    const float* wllr  = (const float*)d_in[5];
    const float* mwde  = (const float*)d_in[6];
    const float* mwllr = (const float*)d_in[7];
    const float* rhos  = (const float*)d_in[8];
    const float* resw  = (const float*)d_in[9];
    float* out = (float*)d_out;

    cudaFuncSetAttribute(k_main, cudaFuncAttributeMaxDynamicSharedMemorySize, SMEM_BYTES);

    k_prep1<<<Mdim, 512>>>((const float4*)H);
    k_prep2<<<1, Mdim>>>(rhos, out);
    k_prep3<<<CLSZ, 1024>>>();
    k_gather<<<(SLOTS + 255) / 256, 256>>>(wde, mwde);
    k_main<<<Bsz * CLSZ, NTH, SMEM_BYTES>>>(synd, errs, llrs, wllr, mwllr, resw, out);
}

// round 12
// speedup vs baseline: 1.9252x; 1.9252x over previous
#include <cuda_runtime.h>
#include <cooperative_groups.h>
#include <math.h>

namespace cg = cooperative_groups;

#define Mdim 512
#define Ndim 2048
#define Bsz  4
#define Lnum 20
#define CAP  24576            // global nnz cap (E[nnz]=20971)
#define ROWCAP 96
#define MNdim (Mdim*Ndim)
#define EPSV 1e-6f
#define NTH  1024
#define CLSZ 8
#define RPC (Mdim/CLSZ)       // 64 rows per CTA
#define CPC (Ndim/CLSZ)       // 256 cols per CTA
#define LCAP 3328             // per-CTA entry cap (E=2621, sd~51, +13.8 sigma), mult of 4
#define SLOTS (CLSZ*LCAP)     // 26624

#define CLUSTER_ARRIVE() asm volatile("barrier.cluster.arrive.aligned;" ::: "memory")
#define CLUSTER_WAIT()   asm volatile("barrier.cluster.wait.aligned;" ::: "memory")

// ---------------- device scratch ----------------
__device__ int            g_deg[Mdim];
__device__ int            g_rowptr[Mdim + 1];
__device__ int            g_nnz;
__device__ unsigned short g_stage[Mdim * ROWCAP];
__device__ unsigned       g_lin[CAP];          // CSR linear indices
__device__ unsigned short g_permS[SLOTS];      // slice-local CSC pos -> local CSR pos
__device__ unsigned       g_linS[SLOTS];       // slice-local CSC linear indices
__device__ int            g_scnt[CLSZ];
__device__ int            g_colptr[CLSZ * (Ndim + 1)];
__device__ __align__(16) float2 g_wmn[(size_t)Lnum * SLOTS]; // {mwde[l], wde[l+1]} CSC slice-local
__device__ float          g_rho[Lnum];

__device__ __forceinline__ void cpasync16(unsigned dst, const void* src) {
    asm volatile("cp.async.ca.shared.global [%0], [%1], 16;" :: "r"(dst), "l"(src));
}

// ---------------- P1: block per row — degree + staged column list ----------------
__global__ void k_prep1(const float4* __restrict__ H4) {
    __shared__ int s_cnt;
    __shared__ unsigned short s_cols[ROWCAP];
    const int i = blockIdx.x;
    const int t = threadIdx.x;       // 512 threads, one float4 each
    const int lane = t & 31;
    if (t == 0) s_cnt = 0;
    __syncthreads();
    float4 v = H4[(size_t)i * (Ndim / 4) + t];
    int cnt = (v.x != 0.0f) + (v.y != 0.0f) + (v.z != 0.0f) + (v.w != 0.0f);
    int sc = cnt;
    for (int o = 1; o < 32; o <<= 1) {
        int u = __shfl_up_sync(0xffffffffu, sc, o);
        if (lane >= o) sc += u;
    }
    int total = __shfl_sync(0xffffffffu, sc, 31);
    int base = 0;
    if (lane == 31 && total) base = atomicAdd(&s_cnt, total);
    base = __shfl_sync(0xffffffffu, base, 31);
    int idx = base + sc - cnt;
    int c = t * 4;
    if (v.x != 0.0f && idx < ROWCAP) s_cols[idx++] = (unsigned short)c;
    if (v.y != 0.0f && idx < ROWCAP) s_cols[idx++] = (unsigned short)(c + 1);
    if (v.z != 0.0f && idx < ROWCAP) s_cols[idx++] = (unsigned short)(c + 2);
    if (v.w != 0.0f && idx < ROWCAP) s_cols[idx++] = (unsigned short)(c + 3);
    __syncthreads();
    int d = min(s_cnt, ROWCAP);
    if (t == 0) g_deg[i] = d;
    if (t < d) g_stage[i * ROWCAP + t] = s_cols[t];
}

// ---------------- P2: scan + expand CSR + softmax + zero out ----------------
__global__ void k_prep2(const float* __restrict__ rhos, float* __restrict__ out) {
    __shared__ int s[Mdim];
    const int t = threadIdx.x;
    s[t] = g_deg[t];
    __syncthreads();
    for (int off = 1; off < Mdim; off <<= 1) {
        int v = (t >= off) ? s[t - off] : 0;
        __syncthreads();
        s[t] += v;
        __syncthreads();
    }
    g_rowptr[t + 1] = s[t];
    if (t == 0) g_rowptr[0] = 0;
    if (t == Mdim - 1) g_nnz = s[Mdim - 1];
    int st = s[t] - g_deg[t];
    int d  = g_deg[t];
    unsigned lbase = (unsigned)(t * Ndim);
    for (int k = 0; k < d; k++) {
        int idx = st + k;
        if (idx < CAP) g_lin[idx] = lbase + g_stage[t * ROWCAP + k];
    }
    if (t == 0) {
        *out = 0.0f;
        float mx = -1e30f;
        for (int l = 0; l < Lnum; l++) mx = fmaxf(mx, rhos[l]);
        float e[Lnum], sm = 0.0f;
        for (int l = 0; l < Lnum; l++) { e[l] = expf(rhos[l] - mx); sm += e[l]; }
        float inv = 1.0f / sm;
        for (int l = 0; l < Lnum; l++) g_rho[l] = e[l] * inv;
    }
}

// ---------------- P3: per-slice CSC (slice-local layout), grid=CLSZ ----------------
__global__ void k_prep3() {
    __shared__ int s_hist[Ndim];
    __shared__ int s_cp[Ndim + 1];
    __shared__ int s_wsum[32];
    const int blk = blockIdx.x;
    const int t = threadIdx.x;
    const int lane = t & 31;
    const int wid = t >> 5;
    const int r0 = blk * RPC;
    const int kbase = g_rowptr[r0];
    int kend = g_rowptr[r0 + RPC];
    if (kend - kbase > LCAP) kend = kbase + LCAP;
    const int cnt = kend - kbase;

    s_hist[t] = 0; s_hist[t + 1024] = 0;
    __syncthreads();
    for (int k = t; k < cnt; k += 1024)
        atomicAdd(&s_hist[g_lin[kbase + k] & (Ndim - 1)], 1);
    __syncthreads();
    int a = s_hist[2 * t], b = s_hist[2 * t + 1];
    int ssum = a + b;
    int sc = ssum;
    for (int o = 1; o < 32; o <<= 1) {
        int u = __shfl_up_sync(0xffffffffu, sc, o);
        if (lane >= o) sc += u;
    }
    if (lane == 31) s_wsum[wid] = sc;
    __syncthreads();
    if (wid == 0) {
        int v = s_wsum[lane];
        for (int o = 1; o < 32; o <<= 1) {
            int u = __shfl_up_sync(0xffffffffu, v, o);
            if (lane >= o) v += u;
        }
        s_wsum[lane] = v;
    }
    __syncthreads();
    int incl = sc + ((wid > 0) ? s_wsum[wid - 1] : 0);
    int excl = incl - ssum;
    s_cp[2 * t] = excl;
    s_cp[2 * t + 1] = excl + a;
    if (t == 1023) s_cp[Ndim] = incl;
    __syncthreads();
    s_hist[2 * t] = s_cp[2 * t];
    s_hist[2 * t + 1] = s_cp[2 * t + 1];
    g_colptr[blk * (Ndim + 1) + 2 * t]     = s_cp[2 * t];
    g_colptr[blk * (Ndim + 1) + 2 * t + 1] = s_cp[2 * t + 1];
    if (t == 1023) g_colptr[blk * (Ndim + 1) + Ndim] = s_cp[Ndim];
    if (t == 0) g_scnt[blk] = cnt;
    __syncthreads();
    for (int k = t; k < cnt; k += 1024) {
        unsigned lin = g_lin[kbase + k];
        int j = lin & (Ndim - 1);
        int pos = atomicAdd(&s_hist[j], 1);
        g_permS[blk * LCAP + pos] = (unsigned short)k;
        g_linS[blk * LCAP + pos]  = lin;
    }
}

// ---------------- P4: gather — one thread per entry, all layers ----------------
__global__ void k_gather(const float* __restrict__ wde, const float* __restrict__ mwde) {
    const int e = blockIdx.x * 256 + threadIdx.x;     // 0..SLOTS-1
    if (e >= SLOTS) return;
    const int blk = e / LCAP;
    const int k = e - blk * LCAP;
    const bool valid = (k < g_scnt[blk]);
    const unsigned lin = valid ? g_linS[e] : 0u;
    float wm[Lnum], wn[Lnum];
    #pragma unroll
    for (int l = 0; l < Lnum; l++) wm[l] = __ldg(&mwde[(size_t)l * MNdim + lin]);
    #pragma unroll
    for (int l = 0; l < Lnum; l++) wn[l] = __ldg(&wde[(size_t)l * MNdim + lin]);
    #pragma unroll
    for (int l = 0; l < Lnum; l++) {
        float2 p;
        p.x = wm[l];
        p.y = (l + 1 < Lnum) ? wn[l + 1] : 0.0f;
        g_wmn[(size_t)l * SLOTS + e] = p;
    }
}

// ---------------- main BP recurrence: CLSZ=8, R10 skeleton ----------------
// floats: msgs LCAP | wmn 2*LCAP | colC N | colP N | belP N | sign2 R | offf R |
//         err C | misc 96 ; int rpt R+4 ; u16: lin LCAP | perm LCAP | cptr N+4
#define SMEM_BYTES ((3*LCAP + 3*Ndim + 2*RPC + CPC + 96 + (RPC + 4)) * 4 \
                    + (2*LCAP + Ndim + 4) * 2)

__global__ void __launch_bounds__(NTH, 1) __cluster_dims__(CLSZ, 1, 1)
k_main(const int*   __restrict__ synd,
       const int*   __restrict__ errs,
       const float* __restrict__ llrs,
       const float* __restrict__ wllr,
       const float* __restrict__ mwllr,
       const float* __restrict__ resw,
       float* __restrict__ out)
{
    extern __shared__ char sm_raw[];
    float*  s_msgs  = (float*)sm_raw;                // LCAP
    float2* s_wmn   = (float2*)(s_msgs + LCAP);      // LCAP float2
    float*  s_colC  = (float*)(s_wmn + LCAP);        // N (combined, read in phase B)
    float*  s_colP  = s_colC + Ndim;                 // N (partials, direct store)
    float*  s_belP  = s_colP + Ndim;                 // N
    float*  s_sign2 = s_belP + Ndim;                 // R
    float*  s_offf  = s_sign2 + RPC;                 // R
    float*  s_err   = s_offf + RPC;                  // C
    float*  s_resw  = s_err + CPC;                   // 32
    float*  s_rho   = s_resw + 32;                   // 32
    float*  s_lacc  = s_rho + 32;                    // 32
    int*    s_rpt   = (int*)(s_lacc + 32);           // R+1 (+pad)
    unsigned short* s_lin  = (unsigned short*)(s_rpt + RPC + 4);  // LCAP
    unsigned short* s_perm = s_lin + LCAP;                         // LCAP
    unsigned short* s_cptr = s_perm + LCAP;                        // N+1 (+pad)

    cg::cluster_group cl = cg::this_cluster();
    const int rank = (int)cl.block_rank();
    const int b    = blockIdx.x / CLSZ;
    const int tid  = threadIdx.x;
    const int lane = tid & 31;
    const int wid  = tid >> 5;
    const float OME = 1.0f - EPSV;
    const unsigned u_wmn = (unsigned)__cvta_generic_to_shared(s_wmn);

    const int r0 = rank * RPC;
    const int kbase = g_rowptr[r0];
    int kend = g_rowptr[r0 + RPC];
    if (kend - kbase > LCAP) kend = kbase + LCAP;
    const int cnt = kend - kbase;
    const int n16 = (cnt + 1) >> 1;     // 16B chunks (2 float2 per chunk)

    // ---- prologue ----
    for (int k = tid; k < cnt; k += NTH) {
        s_lin[k]  = (unsigned short)(g_lin[kbase + k] & (Ndim - 1));
        s_perm[k] = g_permS[rank * LCAP + k];
        s_msgs[k] = 0.0f;
    }
    for (int j = tid; j <= Ndim; j += NTH)
        s_cptr[j] = (unsigned short)g_colptr[rank * (Ndim + 1) + j];
    if (tid <= RPC) s_rpt[tid] = g_rowptr[r0 + tid] - kbase;
    if (tid < RPC) {
        int row = r0 + tid;
        s_sign2[tid] = 2.0f * (1.0f - 2.0f * (float)synd[b * Mdim + row]);
        int d = g_rowptr[row + 1] - g_rowptr[row];
        s_offf[tid] = powf(OME, (float)(Ndim - d));
    }
    if (tid < CPC)
        s_err[tid] = 1.0f - (float)errs[b * Ndim + rank * CPC + tid];
    if (tid < Lnum) { s_resw[tid] = resw[tid]; s_rho[tid] = g_rho[tid]; }
    for (int j = tid; j < Ndim; j += NTH)
        s_colC[j] = llrs[j] * wllr[j];     // layer-0 combined column input
    __syncthreads();

    float acc = 0.0f;
    for (int l = 0; l < Lnum; l++) {
        const float rw = s_resw[l];
        const bool lastL = (l == Lnum - 1);

        // ---- stage this layer's float2 weights (coalesced 16B cp.async) ----
        {
            const float2* src = &g_wmn[(size_t)l * SLOTS + rank * LCAP];
            for (int q = tid; q < n16; q += NTH)
                cpasync16(u_wmn + (unsigned)q * 16u, src + q * 2);
            asm volatile("cp.async.commit_group;");
        }

        // ---- phase B: fused warp-per-row (tanh + product + message update), 2 rows/warp ----
        #pragma unroll
        for (int rr = wid; rr < RPC; rr += 32) {
            const int st = s_rpt[rr], en = s_rpt[rr + 1];
            const int k0 = st + lane, k1 = k0 + 32, k2 = k1 + 32;
            float d0 = 1.0f, d1 = 1.0f, d2 = 1.0f;
            float prod = 1.0f;
            if (k0 < en) {
                float men = s_colC[s_lin[k0]] - s_msgs[k0];
                asm("tanh.approx.f32 %0, %1;" : "=f"(d0) : "f"(0.5f * men));
                if (d0 == 0.0f) d0 = 1.0f;
                d0 = fminf(fmaxf(d0, -OME), OME);
                prod *= d0;
            }
            if (k1 < en) {
                float men = s_colC[s_lin[k1]] - s_msgs[k1];
                asm("tanh.approx.f32 %0, %1;" : "=f"(d1) : "f"(0.5f * men));
                if (d1 == 0.0f) d1 = 1.0f;
                d1 = fminf(fmaxf(d1, -OME), OME);
                prod *= d1;
            }
            if (k2 < en) {
                float men = s_colC[s_lin[k2]] - s_msgs[k2];
                asm("tanh.approx.f32 %0, %1;" : "=f"(d2) : "f"(0.5f * men));
                if (d2 == 0.0f) d2 = 1.0f;
                d2 = fminf(fmaxf(d2, -OME), OME);
                prod *= d2;
            }
            #pragma unroll
            for (int o = 16; o; o >>= 1) prod *= __shfl_xor_sync(0xffffffffu, prod, o);
            const float P = prod * s_offf[rr];
            const float sg = s_sign2[rr];
            if (k0 < en) {
                float r = __fdividef(P, d0);
                float ath = (fabsf(r) < 6.25e-3f) ? r * (1.0f + (1.0f / 3.0f) * r * r)
                                                  : atanhf(r);
                s_msgs[k0] = sg * ath + rw * s_msgs[k0];
            }
            if (k1 < en) {
                float r = __fdividef(P, d1);
                float ath = (fabsf(r) < 6.25e-3f) ? r * (1.0f + (1.0f / 3.0f) * r * r)
                                                  : atanhf(r);
                s_msgs[k1] = sg * ath + rw * s_msgs[k1];
            }
            if (k2 < en) {
                float r = __fdividef(P, d2);
                float ath = (fabsf(r) < 6.25e-3f) ? r * (1.0f + (1.0f / 3.0f) * r * r)
                                                  : atanhf(r);
                s_msgs[k2] = sg * ath + rw * s_msgs[k2];
            }
        }
        asm volatile("cp.async.wait_group 0;" ::: "memory");
        __syncthreads();   // msgs + staged weights visible to all

        // ---- phase C: column-parallel CSC partial sums (2 cols/thread) ----
        {
            const int j0 = tid * 2;
            #pragma unroll
            for (int jj = 0; jj < 2; jj++) {
                const int j = j0 + jj;
                const int st = s_cptr[j], en = s_cptr[j + 1];
                float cs = 0.0f, bs = 0.0f;
                for (int t = st; t < en; t++) {
                    float m = s_msgs[s_perm[t]];
                    float2 w = s_wmn[t];
                    bs += m * w.x;
                    cs += m * w.y;
                }
                s_belP[j] = bs;
                s_colP[j] = cs;
            }
        }
        CLUSTER_ARRIVE();
        CLUSTER_WAIT();

        // ---- cluster combine (slice-owned, float4 DSMEM, 8 peers) + loss ----
        if (tid < CPC / 4) {                 // 64 threads: column combine + broadcast
            if (!lastL) {
                int f4 = rank * (CPC / 4) + tid;
                float4 lv = ((const float4*)llrs)[f4];
                float4 wv = ((const float4*)(wllr + (size_t)(l + 1) * Ndim))[f4];
                float4 s;
                s.x = lv.x * wv.x; s.y = lv.y * wv.y;
                s.z = lv.z * wv.z; s.w = lv.w * wv.w;
                #pragma unroll
                for (int r = 0; r < CLSZ; r++) {
                    float4 p = ((const float4*)cl.map_shared_rank(s_colP, r))[f4];
                    s.x += p.x; s.y += p.y; s.z += p.z; s.w += p.w;
                }
                #pragma unroll
                for (int r = 0; r < CLSZ; r++)
                    ((float4*)cl.map_shared_rank(s_colC, r))[f4] = s;
            }
        } else if (tid < 2 * (CPC / 4)) {    // 64 threads: belief combine + loss
            int f4l = tid - CPC / 4;
            int f4 = rank * (CPC / 4) + f4l;
            float4 lv = ((const float4*)llrs)[f4];
            float4 wv = ((const float4*)(mwllr + (size_t)l * Ndim))[f4];
            float4 x;
            x.x = lv.x * wv.x; x.y = lv.y * wv.y;
            x.z = lv.z * wv.z; x.w = lv.w * wv.w;
            #pragma unroll
            for (int r = 0; r < CLSZ; r++) {
                float4 p = ((const float4*)cl.map_shared_rank(s_belP, r))[f4];
                x.x += p.x; x.y += p.y; x.z += p.z; x.w += p.w;
            }
            int jj = f4l * 4;
            float ls = 0.0f;
            ls += fmaxf(x.x, 0.0f) + log1pf(__expf(-fabsf(x.x))) - s_err[jj]     * x.x;
            ls += fmaxf(x.y, 0.0f) + log1pf(__expf(-fabsf(x.y))) - s_err[jj + 1] * x.y;
            ls += fmaxf(x.z, 0.0f) + log1pf(__expf(-fabsf(x.z))) - s_err[jj + 2] * x.z;
            ls += fmaxf(x.w, 0.0f) + log1pf(__expf(-fabsf(x.w))) - s_err[jj + 3] * x.w;
            acc += s_rho[l] * ls;
        }
        CLUSTER_ARRIVE();
        CLUSTER_WAIT();
    }

    // ---- loss reduce: acc lives in warps 2..3 (threads 64..127) ----
    for (int o = 16; o; o >>= 1) acc += __shfl_xor_sync(0xffffffffu, acc, o);
    if (wid >= 2 && wid < 4 && lane == 0) s_lacc[wid - 2] = acc;
    __syncthreads();
    if (tid == 0) {
        float s = s_lacc[0] + s_lacc[1];
        atomicAdd(out, s * (1.0f / (float)Bsz));
    }
}

// ---------------- host launcher ----------------
extern "C" void kernel_launch(void* const* d_in, const int* in_sizes, int n_in,
                              void* d_out, int out_size) {
    const int*   synd  = (const int*)d_in[0];
    const int*   errs  = (const int*)d_in[1];
    const float* H     = (const float*)d_in[2];
    const float* llrs  = (const float*)d_in[3];
    const float* wde   = (const float*)d_in[4];
    const float* wllr  = (const float*)d_in[5];
    const float* mwde  = (const float*)d_in[6];
    const float* mwllr = (const float*)d_in[7];
    const float* rhos  = (const float*)d_in[8];
    const float* resw  = (const float*)d_in[9];
    float* out = (float*)d_out;

    cudaFuncSetAttribute(k_main, cudaFuncAttributeMaxDynamicSharedMemorySize, SMEM_BYTES);

    k_prep1<<<Mdim, 512>>>((const float4*)H);
    k_prep2<<<1, Mdim>>>(rhos, out);
    k_prep3<<<CLSZ, 1024>>>();
    k_gather<<<(SLOTS + 255) / 256, 256>>>(wde, mwde);
    k_main<<<Bsz * CLSZ, NTH, SMEM_BYTES>>>(synd, errs, llrs, wllr, mwllr, resw, out);
}

// round 13
// speedup vs baseline: 1.9801x; 1.0285x over previous
#include <cuda_runtime.h>
#include <cooperative_groups.h>
#include <math.h>

namespace cg = cooperative_groups;

#define Mdim 512
#define Ndim 2048
#define Bsz  4
#define Lnum 20
#define CAP  24576            // global nnz cap (E[nnz]=20971)
#define ROWCAP 96
#define MNdim (Mdim*Ndim)
#define EPSV 1e-6f
#define NTH  1024
#define CLSZ 16
#define RPC (Mdim/CLSZ)       // 32 rows per CTA
#define CPC (Ndim/CLSZ)       // 128 cols per CTA
#define LCAP 1792             // per-CTA entry cap (E=1311, sd~36, +13.4 sigma), mult of 4
#define SLOTS (CLSZ*LCAP)     // 28672

#define CLUSTER_ARRIVE() asm volatile("barrier.cluster.arrive.aligned;" ::: "memory")
#define CLUSTER_WAIT()   asm volatile("barrier.cluster.wait.aligned;" ::: "memory")

// ---------------- device scratch ----------------
__device__ int            g_deg[Mdim];
__device__ int            g_rowptr[Mdim + 1];
__device__ int            g_nnz;
__device__ unsigned short g_stage[Mdim * ROWCAP];
__device__ unsigned       g_lin[CAP];          // CSR linear indices
__device__ unsigned short g_permS[SLOTS];      // slice-local CSC pos -> local CSR pos
__device__ unsigned       g_linS[SLOTS];       // slice-local CSC linear indices
__device__ int            g_scnt[CLSZ];
__device__ int            g_colptr[CLSZ * (Ndim + 1)];
__device__ __align__(16) float2 g_wmn[(size_t)Lnum * SLOTS]; // {mwde[l], wde[l+1]} CSC slice-local
__device__ float          g_rho[Lnum];

__device__ __forceinline__ void cpasync16(unsigned dst, const void* src) {
    asm volatile("cp.async.ca.shared.global [%0], [%1], 16;" :: "r"(dst), "l"(src));
}

// ---------------- P1: block per row — degree + staged column list ----------------
__global__ void k_prep1(const float4* __restrict__ H4) {
    __shared__ int s_cnt;
    __shared__ unsigned short s_cols[ROWCAP];
    const int i = blockIdx.x;
    const int t = threadIdx.x;       // 512 threads, one float4 each
    const int lane = t & 31;
    if (t == 0) s_cnt = 0;
    __syncthreads();
    float4 v = H4[(size_t)i * (Ndim / 4) + t];
    int cnt = (v.x != 0.0f) + (v.y != 0.0f) + (v.z != 0.0f) + (v.w != 0.0f);
    int sc = cnt;
    for (int o = 1; o < 32; o <<= 1) {
        int u = __shfl_up_sync(0xffffffffu, sc, o);
        if (lane >= o) sc += u;
    }
    int total = __shfl_sync(0xffffffffu, sc, 31);
    int base = 0;
    if (lane == 31 && total) base = atomicAdd(&s_cnt, total);
    base = __shfl_sync(0xffffffffu, base, 31);
    int idx = base + sc - cnt;
    int c = t * 4;
    if (v.x != 0.0f && idx < ROWCAP) s_cols[idx++] = (unsigned short)c;
    if (v.y != 0.0f && idx < ROWCAP) s_cols[idx++] = (unsigned short)(c + 1);
    if (v.z != 0.0f && idx < ROWCAP) s_cols[idx++] = (unsigned short)(c + 2);
    if (v.w != 0.0f && idx < ROWCAP) s_cols[idx++] = (unsigned short)(c + 3);
    __syncthreads();
    int d = min(s_cnt, ROWCAP);
    if (t == 0) g_deg[i] = d;
    if (t < d) g_stage[i * ROWCAP + t] = s_cols[t];
}

// ---------------- P2: scan + expand CSR + softmax + zero out ----------------
__global__ void k_prep2(const float* __restrict__ rhos, float* __restrict__ out) {
    __shared__ int s[Mdim];
    const int t = threadIdx.x;
    s[t] = g_deg[t];
    __syncthreads();
    for (int off = 1; off < Mdim; off <<= 1) {
        int v = (t >= off) ? s[t - off] : 0;
        __syncthreads();
        s[t] += v;
        __syncthreads();
    }
    g_rowptr[t + 1] = s[t];
    if (t == 0) g_rowptr[0] = 0;
    if (t == Mdim - 1) g_nnz = s[Mdim - 1];
    int st = s[t] - g_deg[t];
    int d  = g_deg[t];
    unsigned lbase = (unsigned)(t * Ndim);
    for (int k = 0; k < d; k++) {
        int idx = st + k;
        if (idx < CAP) g_lin[idx] = lbase + g_stage[t * ROWCAP + k];
    }
    if (t == 0) {
        *out = 0.0f;
        float mx = -1e30f;
        for (int l = 0; l < Lnum; l++) mx = fmaxf(mx, rhos[l]);
        float e[Lnum], sm = 0.0f;
        for (int l = 0; l < Lnum; l++) { e[l] = expf(rhos[l] - mx); sm += e[l]; }
        float inv = 1.0f / sm;
        for (int l = 0; l < Lnum; l++) g_rho[l] = e[l] * inv;
    }
}

// ---------------- P3: per-slice CSC (slice-local layout), grid=CLSZ ----------------
__global__ void k_prep3() {
    __shared__ int s_hist[Ndim];
    __shared__ int s_cp[Ndim + 1];
    __shared__ int s_wsum[32];
    const int blk = blockIdx.x;
    const int t = threadIdx.x;
    const int lane = t & 31;
    const int wid = t >> 5;
    const int r0 = blk * RPC;
    const int kbase = g_rowptr[r0];
    int kend = g_rowptr[r0 + RPC];
    if (kend - kbase > LCAP) kend = kbase + LCAP;
    const int cnt = kend - kbase;

    s_hist[t] = 0; s_hist[t + 1024] = 0;
    __syncthreads();
    for (int k = t; k < cnt; k += 1024)
        atomicAdd(&s_hist[g_lin[kbase + k] & (Ndim - 1)], 1);
    __syncthreads();
    int a = s_hist[2 * t], b = s_hist[2 * t + 1];
    int ssum = a + b;
    int sc = ssum;
    for (int o = 1; o < 32; o <<= 1) {
        int u = __shfl_up_sync(0xffffffffu, sc, o);
        if (lane >= o) sc += u;
    }
    if (lane == 31) s_wsum[wid] = sc;
    __syncthreads();
    if (wid == 0) {
        int v = s_wsum[lane];
        for (int o = 1; o < 32; o <<= 1) {
            int u = __shfl_up_sync(0xffffffffu, v, o);
            if (lane >= o) v += u;
        }
        s_wsum[lane] = v;
    }
    __syncthreads();
    int incl = sc + ((wid > 0) ? s_wsum[wid - 1] : 0);
    int excl = incl - ssum;
    s_cp[2 * t] = excl;
    s_cp[2 * t + 1] = excl + a;
    if (t == 1023) s_cp[Ndim] = incl;
    __syncthreads();
    s_hist[2 * t] = s_cp[2 * t];
    s_hist[2 * t + 1] = s_cp[2 * t + 1];
    g_colptr[blk * (Ndim + 1) + 2 * t]     = s_cp[2 * t];
    g_colptr[blk * (Ndim + 1) + 2 * t + 1] = s_cp[2 * t + 1];
    if (t == 1023) g_colptr[blk * (Ndim + 1) + Ndim] = s_cp[Ndim];
    if (t == 0) g_scnt[blk] = cnt;
    __syncthreads();
    for (int k = t; k < cnt; k += 1024) {
        unsigned lin = g_lin[kbase + k];
        int j = lin & (Ndim - 1);
        int pos = atomicAdd(&s_hist[j], 1);
        g_permS[blk * LCAP + pos] = (unsigned short)k;
        g_linS[blk * LCAP + pos]  = lin;
    }
}

// ---------------- P4: gather — one thread per (entry, layer-half) ----------------
#define GHALF (Lnum / 2)    // 10 layers per thread
__global__ void k_gather(const float* __restrict__ wde, const float* __restrict__ mwde) {
    const int nb = (SLOTS + 255) / 256;
    const int half = blockIdx.x / nb;               // 0 or 1
    const int e = (blockIdx.x - half * nb) * 256 + threadIdx.x;
    if (e >= SLOTS) return;
    const int blk = e / LCAP;
    const int k = e - blk * LCAP;
    const bool valid = (k < g_scnt[blk]);
    const unsigned lin = valid ? g_linS[e] : 0u;
    const int l0 = half * GHALF;
    float wm[GHALF], wn[GHALF];
    #pragma unroll
    for (int i = 0; i < GHALF; i++) wm[i] = __ldg(&mwde[(size_t)(l0 + i) * MNdim + lin]);
    #pragma unroll
    for (int i = 0; i < GHALF; i++) {
        int ln = l0 + i + 1;
        wn[i] = (ln < Lnum) ? __ldg(&wde[(size_t)ln * MNdim + lin]) : 0.0f;
    }
    #pragma unroll
    for (int i = 0; i < GHALF; i++) {
        float2 p; p.x = wm[i]; p.y = wn[i];
        g_wmn[(size_t)(l0 + i) * SLOTS + e] = p;
    }
}

// ---------------- main BP recurrence: CLSZ=16, R12 skeleton ----------------
// floats: msgs LCAP | wmn 2*LCAP | colC N | colP N | belP N | sign2 R | offf R |
//         err C | misc 96 ; int rpt R+4 ; u16: lin LCAP | perm LCAP | cptr N+4
#define SMEM_BYTES ((3*LCAP + 3*Ndim + 2*RPC + CPC + 96 + (RPC + 4)) * 4 \
                    + (2*LCAP + Ndim + 4) * 2)

__global__ void __launch_bounds__(NTH, 1) __cluster_dims__(CLSZ, 1, 1)
k_main(const int*   __restrict__ synd,
       const int*   __restrict__ errs,
       const float* __restrict__ llrs,
       const float* __restrict__ wllr,
       const float* __restrict__ mwllr,
       const float* __restrict__ resw,
       float* __restrict__ out)
{
    extern __shared__ char sm_raw[];
    float*  s_msgs  = (float*)sm_raw;                // LCAP
    float2* s_wmn   = (float2*)(s_msgs + LCAP);      // LCAP float2
    float*  s_colC  = (float*)(s_wmn + LCAP);        // N (combined, read in phase B)
    float*  s_colP  = s_colC + Ndim;                 // N (partials, direct store)
    float*  s_belP  = s_colP + Ndim;                 // N
    float*  s_sign2 = s_belP + Ndim;                 // R
    float*  s_offf  = s_sign2 + RPC;                 // R
    float*  s_err   = s_offf + RPC;                  // C
    float*  s_resw  = s_err + CPC;                   // 32
    float*  s_rho   = s_resw + 32;                   // 32
    float*  s_lacc  = s_rho + 32;                    // 32
    int*    s_rpt   = (int*)(s_lacc + 32);           // R+1 (+pad)
    unsigned short* s_lin  = (unsigned short*)(s_rpt + RPC + 4);  // LCAP
    unsigned short* s_perm = s_lin + LCAP;                         // LCAP
    unsigned short* s_cptr = s_perm + LCAP;                        // N+1 (+pad)

    cg::cluster_group cl = cg::this_cluster();
    const int rank = (int)cl.block_rank();
    const int b    = blockIdx.x / CLSZ;
    const int tid  = threadIdx.x;
    const int lane = tid & 31;
    const int wid  = tid >> 5;
    const float OME = 1.0f - EPSV;
    const unsigned u_wmn = (unsigned)__cvta_generic_to_shared(s_wmn);

    const int r0 = rank * RPC;
    const int kbase = g_rowptr[r0];
    int kend = g_rowptr[r0 + RPC];
    if (kend - kbase > LCAP) kend = kbase + LCAP;
    const int cnt = kend - kbase;
    const int n16 = (cnt + 1) >> 1;     // 16B chunks (2 float2 per chunk)

    // ---- prologue ----
    for (int k = tid; k < cnt; k += NTH) {
        s_lin[k]  = (unsigned short)(g_lin[kbase + k] & (Ndim - 1));
        s_perm[k] = g_permS[rank * LCAP + k];
        s_msgs[k] = 0.0f;
    }
    for (int j = tid; j <= Ndim; j += NTH)
        s_cptr[j] = (unsigned short)g_colptr[rank * (Ndim + 1) + j];
    if (tid <= RPC) s_rpt[tid] = g_rowptr[r0 + tid] - kbase;
    if (tid < RPC) {
        int row = r0 + tid;
        s_sign2[tid] = 2.0f * (1.0f - 2.0f * (float)synd[b * Mdim + row]);
        int d = g_rowptr[row + 1] - g_rowptr[row];
        s_offf[tid] = powf(OME, (float)(Ndim - d));
    }
    if (tid < CPC)
        s_err[tid] = 1.0f - (float)errs[b * Ndim + rank * CPC + tid];
    if (tid < Lnum) { s_resw[tid] = resw[tid]; s_rho[tid] = g_rho[tid]; }
    for (int j = tid; j < Ndim; j += NTH)
        s_colC[j] = llrs[j] * wllr[j];     // layer-0 combined column input
    __syncthreads();

    float acc = 0.0f;
    for (int l = 0; l < Lnum; l++) {
        const float rw = s_resw[l];
        const bool lastL = (l == Lnum - 1);

        // ---- stage this layer's float2 weights (coalesced 16B cp.async) ----
        {
            const float2* src = &g_wmn[(size_t)l * SLOTS + rank * LCAP];
            for (int q = tid; q < n16; q += NTH)
                cpasync16(u_wmn + (unsigned)q * 16u, src + q * 2);
            asm volatile("cp.async.commit_group;");
        }

        // ---- phase B: fused warp-per-row (1 row/warp) ----
        if (wid < RPC) {
            const int rr = wid;
            const int st = s_rpt[rr], en = s_rpt[rr + 1];
            const int k0 = st + lane, k1 = k0 + 32, k2 = k1 + 32;
            float d0 = 1.0f, d1 = 1.0f, d2 = 1.0f;
            float prod = 1.0f;
            if (k0 < en) {
                float men = s_colC[s_lin[k0]] - s_msgs[k0];
                asm("tanh.approx.f32 %0, %1;" : "=f"(d0) : "f"(0.5f * men));
                if (d0 == 0.0f) d0 = 1.0f;
                d0 = fminf(fmaxf(d0, -OME), OME);
                prod *= d0;
            }
            if (k1 < en) {
                float men = s_colC[s_lin[k1]] - s_msgs[k1];
                asm("tanh.approx.f32 %0, %1;" : "=f"(d1) : "f"(0.5f * men));
                if (d1 == 0.0f) d1 = 1.0f;
                d1 = fminf(fmaxf(d1, -OME), OME);
                prod *= d1;
            }
            if (k2 < en) {
                float men = s_colC[s_lin[k2]] - s_msgs[k2];
                asm("tanh.approx.f32 %0, %1;" : "=f"(d2) : "f"(0.5f * men));
                if (d2 == 0.0f) d2 = 1.0f;
                d2 = fminf(fmaxf(d2, -OME), OME);
                prod *= d2;
            }
            #pragma unroll
            for (int o = 16; o; o >>= 1) prod *= __shfl_xor_sync(0xffffffffu, prod, o);
            const float P = prod * s_offf[rr];
            const float sg = s_sign2[rr];
            if (k0 < en) {
                float r = __fdividef(P, d0);
                float ath = (fabsf(r) < 6.25e-3f) ? r * (1.0f + (1.0f / 3.0f) * r * r)
                                                  : atanhf(r);
                s_msgs[k0] = sg * ath + rw * s_msgs[k0];
            }
            if (k1 < en) {
                float r = __fdividef(P, d1);
                float ath = (fabsf(r) < 6.25e-3f) ? r * (1.0f + (1.0f / 3.0f) * r * r)
                                                  : atanhf(r);
                s_msgs[k1] = sg * ath + rw * s_msgs[k1];
            }
            if (k2 < en) {
                float r = __fdividef(P, d2);
                float ath = (fabsf(r) < 6.25e-3f) ? r * (1.0f + (1.0f / 3.0f) * r * r)
                                                  : atanhf(r);
                s_msgs[k2] = sg * ath + rw * s_msgs[k2];
            }
        }
        asm volatile("cp.async.wait_group 0;" ::: "memory");
        __syncthreads();   // msgs + staged weights visible to all

        // ---- phase C: column-parallel CSC partial sums (2 cols/thread) ----
        {
            const int j0 = tid * 2;
            #pragma unroll
            for (int jj = 0; jj < 2; jj++) {
                const int j = j0 + jj;
                const int st = s_cptr[j], en = s_cptr[j + 1];
                float cs = 0.0f, bs = 0.0f;
                for (int t = st; t < en; t++) {
                    float m = s_msgs[s_perm[t]];
                    float2 w = s_wmn[t];
                    bs += m * w.x;
                    cs += m * w.y;
                }
                s_belP[j] = bs;
                s_colP[j] = cs;
            }
        }
        CLUSTER_ARRIVE();
        CLUSTER_WAIT();

        // ---- cluster combine (slice-owned, float4 DSMEM, 16 peers) + loss ----
        if (tid < CPC / 4) {                 // 32 threads: column combine + broadcast
            if (!lastL) {
                int f4 = rank * (CPC / 4) + tid;
                float4 lv = ((const float4*)llrs)[f4];
                float4 wv = ((const float4*)(wllr + (size_t)(l + 1) * Ndim))[f4];
                float4 s;
                s.x = lv.x * wv.x; s.y = lv.y * wv.y;
                s.z = lv.z * wv.z; s.w = lv.w * wv.w;
                #pragma unroll
                for (int r = 0; r < CLSZ; r++) {
                    float4 p = ((const float4*)cl.map_shared_rank(s_colP, r))[f4];
                    s.x += p.x; s.y += p.y; s.z += p.z; s.w += p.w;
                }
                #pragma unroll
                for (int r = 0; r < CLSZ; r++)
                    ((float4*)cl.map_shared_rank(s_colC, r))[f4] = s;
            }
        } else if (tid < 2 * (CPC / 4)) {    // 32 threads: belief combine + loss
            int f4l = tid - CPC / 4;
            int f4 = rank * (CPC / 4) + f4l;
            float4 lv = ((const float4*)llrs)[f4];
            float4 wv = ((const float4*)(mwllr + (size_t)l * Ndim))[f4];
            float4 x;
            x.x = lv.x * wv.x; x.y = lv.y * wv.y;
            x.z = lv.z * wv.z; x.w = lv.w * wv.w;
            #pragma unroll
            for (int r = 0; r < CLSZ; r++) {
                float4 p = ((const float4*)cl.map_shared_rank(s_belP, r))[f4];
                x.x += p.x; x.y += p.y; x.z += p.z; x.w += p.w;
            }
            int jj = f4l * 4;
            float ls = 0.0f;
            ls += fmaxf(x.x, 0.0f) + log1pf(__expf(-fabsf(x.x))) - s_err[jj]     * x.x;
            ls += fmaxf(x.y, 0.0f) + log1pf(__expf(-fabsf(x.y))) - s_err[jj + 1] * x.y;
            ls += fmaxf(x.z, 0.0f) + log1pf(__expf(-fabsf(x.z))) - s_err[jj + 2] * x.z;
            ls += fmaxf(x.w, 0.0f) + log1pf(__expf(-fabsf(x.w))) - s_err[jj + 3] * x.w;
            acc += s_rho[l] * ls;
        }
        CLUSTER_ARRIVE();
        CLUSTER_WAIT();
    }

    // ---- loss reduce: acc lives in warp 1 (threads 32..63) ----
    for (int o = 16; o; o >>= 1) acc += __shfl_xor_sync(0xffffffffu, acc, o);
    if (wid == 1 && lane == 0) s_lacc[0] = acc;
    __syncthreads();
    if (tid == 0) atomicAdd(out, s_lacc[0] * (1.0f / (float)Bsz));
}

// ---------------- host launcher ----------------
extern "C" void kernel_launch(void* const* d_in, const int* in_sizes, int n_in,
                              void* d_out, int out_size) {
    const int*   synd  = (const int*)d_in[0];
    const int*   errs  = (const int*)d_in[1];
    const float* H     = (const float*)d_in[2];
    const float* llrs  = (const float*)d_in[3];
    const float* wde   = (const float*)d_in[4];
    const float* wllr  = (const float*)d_in[5];
    const float* mwde  = (const float*)d_in[6];
    const float* mwllr = (const float*)d_in[7];
    const float* rhos  = (const float*)d_in[8];
    const float* resw  = (const float*)d_in[9];
    float* out = (float*)d_out;

    cudaFuncSetAttribute(k_main, cudaFuncAttributeMaxDynamicSharedMemorySize, SMEM_BYTES);
    cudaFuncSetAttribute(k_main, cudaFuncAttributeNonPortableClusterSizeAllowed, 1);

    k_prep1<<<Mdim, 512>>>((const float4*)H);
    k_prep2<<<1, Mdim>>>(rhos, out);
    k_prep3<<<CLSZ, 1024>>>();
    k_gather<<<2 * ((SLOTS + 255) / 256), 256>>>(wde, mwde);
    k_main<<<Bsz * CLSZ, NTH, SMEM_BYTES>>>(synd, errs, llrs, wllr, mwllr, resw, out);
}